// round 1
// baseline (speedup 1.0000x reference)
#include <cuda_runtime.h>

#define BB 8
#define CC 64
#define HH 256
#define WWI 256
#define MO 16
#define HWN 65536
#define NDEPTH 4

// ---------------- scratch (device globals; no allocation allowed) ----------------
__device__ float  g_h0[BB*CC*HWN];                 // 128 MB
__device__ float  g_h1[BB*CC*HWN];                 // 128 MB
__device__ float2 g_f1[BB*CC*HH*MO];               // 16.8 MB
__device__ float2 g_modes[BB*CC*MO*MO];            // 1 MB
__device__ float2 g_mixed[BB*CC*MO*MO];            // 1 MB
__device__ float2 g_G[BB*CC*HH*MO];                // 16.8 MB
__device__ float2 g_wt[NDEPTH*MO*MO*CC*CC];        // 33.5 MB  [d][kx*16+ky][i][o]

// ---------------- weight transpose: [d][i][o][kx][ky] -> [d][m][i][o] ----------------
__global__ void ktw(const float* __restrict__ wre, const float* __restrict__ wim) {
    int idx = blockIdx.x * 256 + threadIdx.x;       // 4*64*64*256 total, exact
    int ky = idx & 15;
    int kx = (idx >> 4) & 15;
    int o  = (idx >> 8) & 63;
    int i  = (idx >> 14) & 63;
    int d  = idx >> 20;
    int m  = kx * 16 + ky;
    g_wt[((d * 256 + m) * 64 + i) * 64 + o] = make_float2(wre[idx], wim[idx]);
}

// ---------------- fc0: 3 -> 64 channels ----------------
__global__ void kfc0(const float* __restrict__ x, const float* __restrict__ w,
                     const float* __restrict__ bv, float* __restrict__ out) {
    int idx = blockIdx.x * 256 + threadIdx.x;       // < 8*64*65536
    int p = idx & (HWN - 1);
    int c = (idx >> 16) & 63;
    int b = idx >> 22;
    const float* xb = x + (size_t)b * 3 * HWN + p;
    out[idx] = bv[c] + xb[0] * w[c*3] + xb[HWN] * w[c*3+1] + xb[2*HWN] * w[c*3+2];
}

// ---------------- forward DFT along W (256 -> 16 modes) ----------------
__global__ void kfwd1(const float* __restrict__ hin, float2* __restrict__ f1) {
    __shared__ float sv[8][257];
    __shared__ float ct[256], st[256];
    int tid = threadIdx.x;                           // 128
    for (int t = tid; t < 256; t += 128) {
        float ang = 6.283185307179586f * (float)t / 256.f;
        ct[t] = cosf(ang); st[t] = sinf(ang);
    }
    long base = (long)blockIdx.x * 8;                // 8 rows per block
    const float* src = hin + base * WWI;
    for (int idx = tid; idx < 8 * 256; idx += 128)
        sv[idx >> 8][idx & 255] = src[idx];
    __syncthreads();
    int r = tid & 7, ky = tid >> 3;
    float re = 0.f, im = 0.f;
    #pragma unroll 16
    for (int x = 0; x < 256; ++x) {
        float v = sv[r][x];
        int t = (ky * x) & 255;
        re = fmaf(v, ct[t], re);                     // e^{-i th} = cos - i sin
        im = fmaf(v, st[t], im);
    }
    f1[(base + r) * MO + ky] = make_float2(re, -im);
}

// ---------------- forward DFT along H (256 -> 16 modes) ----------------
__global__ void kfwd2(const float2* __restrict__ f1, float2* __restrict__ modes) {
    __shared__ float2 sf[4096];
    __shared__ float ct[256], st[256];
    int tid = threadIdx.x;                           // 256
    {
        float ang = 6.283185307179586f * (float)tid / 256.f;
        ct[tid] = cosf(ang); st[tid] = sinf(ang);
    }
    int bc = blockIdx.x;                             // b*64 + c
    const float2* src = f1 + (size_t)bc * 4096;
    for (int idx = tid; idx < 4096; idx += 256) sf[idx] = src[idx];
    __syncthreads();
    int kx = tid >> 4, ky = tid & 15;
    float re = 0.f, im = 0.f;
    #pragma unroll 8
    for (int y = 0; y < 256; ++y) {
        float2 v = sf[y * 16 + ky];
        int t = (kx * y) & 255;
        float c = ct[t], s = st[t];
        re += v.x * c + v.y * s;                     // (vx+ivy)(c-is)
        im += v.y * c - v.x * s;
    }
    modes[bc * 256 + tid] = make_float2(re, im);
}

// ---------------- mode mixing: out[b,o,m] = sum_i modes[b,i,m] * w[i,o,m] ----------------
__global__ void kmix(const float2* __restrict__ modes, const float2* __restrict__ wt,
                     float2* __restrict__ mixed) {
    __shared__ float2 swt[4096];                     // [i][o]
    __shared__ float2 sin_[512];                     // [b][i]
    int tid = threadIdx.x, m = blockIdx.x;
    const float2* wsrc = wt + (size_t)m * 4096;
    for (int idx = tid; idx < 4096; idx += 256) swt[idx] = wsrc[idx];
    for (int idx = tid; idx < 512; idx += 256) {
        int b = idx >> 6, i = idx & 63;
        sin_[idx] = modes[(b * 64 + i) * 256 + m];
    }
    __syncthreads();
    int o = tid & 63;
    for (int half = 0; half < 2; ++half) {
        int b = (tid >> 6) + half * 4;
        float re = 0.f, im = 0.f;
        #pragma unroll 8
        for (int i = 0; i < 64; ++i) {
            float2 a = sin_[b * 64 + i];
            float2 w = swt[i * 64 + o];
            re += a.x * w.x - a.y * w.y;
            im += a.x * w.y + a.y * w.x;
        }
        mixed[(b * 64 + o) * 256 + m] = make_float2(re, im);
    }
}

// ---------------- inverse DFT along H (16 -> 256), e^{+i th}, no 1/H ----------------
__global__ void kinv1(const float2* __restrict__ mixed, float2* __restrict__ G) {
    __shared__ float2 sm[256];
    __shared__ float ct[256], st[256];
    int tid = threadIdx.x;                           // 256
    int bc = blockIdx.x >> 4;
    int yb = (blockIdx.x & 15) << 4;
    {
        float ang = 6.283185307179586f * (float)tid / 256.f;
        ct[tid] = cosf(ang); st[tid] = sinf(ang);
    }
    sm[tid] = mixed[bc * 256 + tid];
    __syncthreads();
    int yy = yb + (tid >> 4), ky = tid & 15;
    float re = 0.f, im = 0.f;
    #pragma unroll
    for (int kx = 0; kx < 16; ++kx) {
        float2 v = sm[kx * 16 + ky];
        int t = (kx * yy) & 255;
        float c = ct[t], s = st[t];
        re += v.x * c - v.y * s;                     // (c+is)(vx+ivy)
        im += v.x * s + v.y * c;
    }
    G[(bc * 256 + yy) * 16 + ky] = make_float2(re, im);
}

// ---------------- fused: 1x1 conv + inverse DFT along W + bias + relu ----------------
// smem floats: sh 64*65 + sw 64*65 + sg 64*17*2 + sA 1024 + sB 1024 + sb 64 = 12608 (50432 B)
__global__ void kfused(const float* __restrict__ hin, const float2* __restrict__ G,
                       const float* __restrict__ ww, const float* __restrict__ wb,
                       float* __restrict__ hout) {
    extern __shared__ float smem[];
    float*  sh = smem;                               // [64][65] input channels tile
    float*  sw = sh + 64 * 65;                       // [64][65] conv weights [o][i]
    float2* sg = (float2*)(sw + 64 * 65);            // [64][17] G[o][ky]
    float*  sA = (float*)(sg + 64 * 17);             // [16][64]
    float*  sB = sA + 1024;                          // [16][64]
    float*  sb = sB + 1024;                          // [64]
    int tid = threadIdx.x;                           // 256
    int xc = (blockIdx.x & 3) << 6;
    int y  = (blockIdx.x >> 2) & 255;
    int b  = blockIdx.x >> 10;

    for (int idx = tid; idx < 4096; idx += 256) {
        int i = idx >> 6, xl = idx & 63;
        sh[i * 65 + xl] = hin[((size_t)(b * 64 + i) * 256 + y) * 256 + xc + xl];
        sw[i * 65 + xl] = ww[idx];                   // [o][i] flat, same decomposition
    }
    for (int idx = tid; idx < 1024; idx += 256) {
        int o = idx >> 4, ky = idx & 15;
        sg[o * 17 + ky] = G[((size_t)(b * 64 + o) * 256 + y) * 16 + ky];
    }
    const float scale = 1.f / 65536.f;               // 1/(H*W)
    for (int idx = tid; idx < 1024; idx += 256) {
        int ky = idx >> 6, xl = idx & 63;
        int t = (ky * (xc + xl)) & 255;
        float ang = 6.283185307179586f * (float)t / 256.f;
        // irfft along W keeping only ky<16; imag of ky=0 bin is ignored (B=0)
        sA[idx] = (ky == 0) ? scale : 2.f * scale * cosf(ang);
        sB[idx] = (ky == 0) ? 0.f   : -2.f * scale * sinf(ang);
    }
    if (tid < 64) sb[tid] = wb[tid];
    __syncthreads();

    int o = tid & 63, xg = tid >> 6;                 // thread: out channel o, x chunk xg*16..+16
    float acc[16];
    float bias = sb[o];
    #pragma unroll
    for (int k = 0; k < 16; ++k) acc[k] = bias;
    // 1x1 conv
    #pragma unroll 4
    for (int i = 0; i < 64; ++i) {
        float wv = sw[o * 65 + i];
        const float* hv = &sh[i * 65 + xg * 16];
        #pragma unroll
        for (int k = 0; k < 16; ++k) acc[k] = fmaf(hv[k], wv, acc[k]);
    }
    // inverse DFT along W
    #pragma unroll 4
    for (int ky = 0; ky < 16; ++ky) {
        float2 g = sg[o * 17 + ky];
        const float* Av = &sA[ky * 64 + xg * 16];
        const float* Bv = &sB[ky * 64 + xg * 16];
        #pragma unroll
        for (int k = 0; k < 16; ++k)
            acc[k] += g.x * Av[k] + g.y * Bv[k];
    }
    __syncthreads();
    #pragma unroll
    for (int k = 0; k < 16; ++k)
        sh[o * 65 + xg * 16 + k] = fmaxf(acc[k], 0.f);
    __syncthreads();
    for (int idx = tid; idx < 4096; idx += 256) {
        int i = idx >> 6, xl = idx & 63;
        hout[((size_t)(b * 64 + i) * 256 + y) * 256 + xc + xl] = sh[i * 65 + xl];
    }
}

// ---------------- fused MLP head: relu(h @ fc1^T + b1) @ fc2^T + b2 ----------------
// smem floats: sh 64*65 + sw1 128*65 + shid 128*65 + sw2 384 + sb1 128 = 21312 (85248 B)
__global__ void khead(const float* __restrict__ hin,
                      const float* __restrict__ w1, const float* __restrict__ b1,
                      const float* __restrict__ w2, const float* __restrict__ b2,
                      float* __restrict__ out) {
    extern __shared__ float smem[];
    float* sh   = smem;                              // [64][65]
    float* sw1  = sh + 64 * 65;                      // [128][65]
    float* shid = sw1 + 128 * 65;                    // [128][65]
    float* sw2  = shid + 128 * 65;                   // [3][128]
    float* sb1  = sw2 + 384;                         // [128]
    int tid = threadIdx.x;                           // 256
    int xc = (blockIdx.x & 3) << 6;
    int y  = (blockIdx.x >> 2) & 255;
    int b  = blockIdx.x >> 10;

    for (int idx = tid; idx < 4096; idx += 256) {
        int c = idx >> 6, xl = idx & 63;
        sh[c * 65 + xl] = hin[((size_t)(b * 64 + c) * 256 + y) * 256 + xc + xl];
    }
    for (int idx = tid; idx < 128 * 64; idx += 256) {
        int m = idx >> 6, c = idx & 63;
        sw1[m * 65 + c] = w1[idx];
    }
    for (int idx = tid; idx < 384; idx += 256) sw2[idx] = w2[idx];
    if (tid < 128) sb1[tid] = b1[tid];
    __syncthreads();

    int m = tid & 127, xg = tid >> 7;                // hidden row m, 32 x's each
    float acc[32];
    float bias = sb1[m];
    #pragma unroll
    for (int k = 0; k < 32; ++k) acc[k] = bias;
    #pragma unroll 4
    for (int c = 0; c < 64; ++c) {
        float wv = sw1[m * 65 + c];
        const float* hv = &sh[c * 65 + xg * 32];
        #pragma unroll
        for (int k = 0; k < 32; ++k) acc[k] = fmaf(hv[k], wv, acc[k]);
    }
    #pragma unroll
    for (int k = 0; k < 32; ++k)
        shid[m * 65 + xg * 32 + k] = fmaxf(acc[k], 0.f);
    __syncthreads();
    if (tid < 192) {
        int o = tid >> 6, xl = tid & 63;
        float a = b2[o];
        #pragma unroll 8
        for (int mm = 0; mm < 128; ++mm)
            a = fmaf(shid[mm * 65 + xl], sw2[o * 128 + mm], a);
        out[((size_t)(b * 3 + o) * 256 + y) * 256 + xc + xl] = a;
    }
}

// ---------------- host ----------------
extern "C" void kernel_launch(void* const* d_in, const int* in_sizes, int n_in,
                              void* d_out, int out_size) {
    const float* x       = (const float*)d_in[0];
    const float* fc0_w   = (const float*)d_in[1];
    const float* fc0_b   = (const float*)d_in[2];
    const float* spec_re = (const float*)d_in[3];
    const float* spec_im = (const float*)d_in[4];
    const float* w_w     = (const float*)d_in[5];
    const float* w_b     = (const float*)d_in[6];
    const float* fc1_w   = (const float*)d_in[7];
    const float* fc1_b   = (const float*)d_in[8];
    const float* fc2_w   = (const float*)d_in[9];
    const float* fc2_b   = (const float*)d_in[10];

    float  *h0, *h1;
    float2 *f1, *mo, *mx, *G, *wt;
    cudaGetSymbolAddress((void**)&h0, g_h0);
    cudaGetSymbolAddress((void**)&h1, g_h1);
    cudaGetSymbolAddress((void**)&f1, g_f1);
    cudaGetSymbolAddress((void**)&mo, g_modes);
    cudaGetSymbolAddress((void**)&mx, g_mixed);
    cudaGetSymbolAddress((void**)&G,  g_G);
    cudaGetSymbolAddress((void**)&wt, g_wt);

    cudaFuncSetAttribute(kfused, cudaFuncAttributeMaxDynamicSharedMemorySize, 50432);
    cudaFuncSetAttribute(khead,  cudaFuncAttributeMaxDynamicSharedMemorySize, 85248);

    ktw<<<16384, 256>>>(spec_re, spec_im);
    kfc0<<<131072, 256>>>(x, fc0_w, fc0_b, h0);

    float* hin = h0;
    float* hout = h1;
    for (int d = 0; d < NDEPTH; ++d) {
        kfwd1<<<16384, 128>>>(hin, f1);
        kfwd2<<<512, 256>>>(f1, mo);
        kmix<<<256, 256>>>(mo, wt + (size_t)d * 256 * 4096, mx);
        kinv1<<<8192, 256>>>(mx, G);
        kfused<<<8192, 256, 50432>>>(hin, G, w_w + d * 4096, w_b + d * 64, hout);
        float* t = hin; hin = hout; hout = t;
    }
    khead<<<8192, 256, 85248>>>(hin, fc1_w, fc1_b, fc2_w, fc2_b, (float*)d_out);
}